// round 6
// baseline (speedup 1.0000x reference)
#include <cuda_runtime.h>
#include <cstdint>

#define H_IN  1024
#define D     64
#define NB    4
#define LSEQ  2048
#define MROWS (NB*LSEQ)     // 8192
#define LDB   72            // smem row stride (bf16 elems): 144B, conflict-free ldmatrix
#define NTILES (LSEQ/64)    // 32

// Pre-split projected tensors (hi/lo bf16). Q is pre-scaled by 1/8.
__device__ uint16_t g_qh[MROWS * D];
__device__ uint16_t g_ql[MROWS * D];
__device__ uint16_t g_kh[MROWS * D];
__device__ uint16_t g_kl[MROWS * D];
__device__ uint16_t g_vh[MROWS * D];
__device__ uint16_t g_vl[MROWS * D];

// ---------------------------------------------------------------------------
// helpers
// ---------------------------------------------------------------------------
__device__ __forceinline__ uint32_t s2u(const void* p) {
    uint32_t a;
    asm("{.reg .u64 t; cvta.to.shared.u64 t, %1; cvt.u32.u64 %0, t;}" : "=r"(a) : "l"(p));
    return a;
}
__device__ __forceinline__ void ldsm_x4(uint32_t* r, uint32_t addr) {
    asm volatile("ldmatrix.sync.aligned.m8n8.x4.shared.b16 {%0,%1,%2,%3}, [%4];"
                 : "=r"(r[0]), "=r"(r[1]), "=r"(r[2]), "=r"(r[3]) : "r"(addr));
}
__device__ __forceinline__ void ldsm_x4_t(uint32_t* r, uint32_t addr) {
    asm volatile("ldmatrix.sync.aligned.m8n8.x4.trans.shared.b16 {%0,%1,%2,%3}, [%4];"
                 : "=r"(r[0]), "=r"(r[1]), "=r"(r[2]), "=r"(r[3]) : "r"(addr));
}
__device__ __forceinline__ void mma16816(float* c, const uint32_t* a, const uint32_t* b) {
    asm volatile("mma.sync.aligned.m16n8k16.row.col.f32.bf16.bf16.f32 "
                 "{%0,%1,%2,%3}, {%4,%5,%6,%7}, {%8,%9}, {%0,%1,%2,%3};"
                 : "+f"(c[0]), "+f"(c[1]), "+f"(c[2]), "+f"(c[3])
                 : "r"(a[0]), "r"(a[1]), "r"(a[2]), "r"(a[3]), "r"(b[0]), "r"(b[1]));
}
// Truncate-split float4 -> bf16x2 hi words + rounded bf16 lo words.
__device__ __forceinline__ void split4(float4 v, uint2& hi, uint2& lo) {
    uint32_t ux = __float_as_uint(v.x), uy = __float_as_uint(v.y);
    uint32_t uz = __float_as_uint(v.z), uw = __float_as_uint(v.w);
    asm("prmt.b32 %0, %1, %2, 0x7632;" : "=r"(hi.x) : "r"(ux), "r"(uy));
    asm("prmt.b32 %0, %1, %2, 0x7632;" : "=r"(hi.y) : "r"(uz), "r"(uw));
    float rx = v.x - __uint_as_float(ux & 0xFFFF0000u);
    float ry = v.y - __uint_as_float(uy & 0xFFFF0000u);
    float rz = v.z - __uint_as_float(uz & 0xFFFF0000u);
    float rw = v.w - __uint_as_float(uw & 0xFFFF0000u);
    asm("cvt.rn.bf16x2.f32 %0, %1, %2;" : "=r"(lo.x) : "f"(ry), "f"(rx));
    asm("cvt.rn.bf16x2.f32 %0, %1, %2;" : "=r"(lo.y) : "f"(rw), "f"(rz));
}
__device__ __forceinline__ uint32_t pack_hi(float a, float b) {
    uint32_t r;
    asm("prmt.b32 %0, %1, %2, 0x7632;" : "=r"(r)
        : "r"(__float_as_uint(a)), "r"(__float_as_uint(b)));
    return r;
}
__device__ __forceinline__ uint32_t pack_lo(float a, float b) {
    float ra = a - __uint_as_float(__float_as_uint(a) & 0xFFFF0000u);
    float rb = b - __uint_as_float(__float_as_uint(b) & 0xFFFF0000u);
    uint32_t r;
    asm("cvt.rn.bf16x2.f32 %0, %1, %2;" : "=r"(r) : "f"(rb), "f"(ra));
    return r;
}
template <int N> __device__ __forceinline__ void cp_wait() {
    asm volatile("cp.async.wait_group %0;" :: "n"(N) : "memory");
}
__device__ __forceinline__ void cp_commit() {
    asm volatile("cp.async.commit_group;" ::: "memory");
}
__device__ __forceinline__ void cp16(uint32_t saddr, const void* gaddr) {
    asm volatile("cp.async.cg.shared.global [%0], [%1], 16;"
                 :: "r"(saddr), "l"(gaddr) : "memory");
}

// ---------------------------------------------------------------------------
// Kernel 1: QKV projection. X(8192x1024) @ W(1024x64) + b -> split hi/lo bf16.
// 128 threads (4 warps), CTA tile M=64, K-chunk 64; grid (128, 3).
// ---------------------------------------------------------------------------
__global__ __launch_bounds__(128) void proj_mma(
    const float* __restrict__ Xq, const float* __restrict__ Xk, const float* __restrict__ Xv,
    const float* __restrict__ Wq, const float* __restrict__ Wk, const float* __restrict__ Wv,
    const float* __restrict__ Bq, const float* __restrict__ Bk, const float* __restrict__ Bv)
{
    const float* X; const float* W; const float* Bias;
    uint16_t* outH; uint16_t* outL; float scale;
    switch (blockIdx.y) {
        case 0:  X = Xq; W = Wq; Bias = Bq; outH = g_qh; outL = g_ql; scale = 0.125f; break;
        case 1:  X = Xk; W = Wk; Bias = Bk; outH = g_kh; outL = g_kl; scale = 1.0f;   break;
        default: X = Xv; W = Wv; Bias = Bv; outH = g_vh; outL = g_vl; scale = 1.0f;   break;
    }

    extern __shared__ uint16_t sp[];
    uint16_t* Ah = sp;                 // [64][LDB]
    uint16_t* Al = Ah + 64 * LDB;
    uint16_t* Bh = Al + 64 * LDB;
    uint16_t* Bl = Bh + 64 * LDB;

    const int tid  = threadIdx.x;
    const int lane = tid & 31;
    const int w    = tid >> 5;
    const int m0   = blockIdx.x * 64;
    const int g    = lane >> 3, l8 = lane & 7;

    float acc[8][4];
    #pragma unroll
    for (int nt = 0; nt < 8; nt++)
        #pragma unroll
        for (int j = 0; j < 4; j++) acc[nt][j] = 0.f;

    float4 xv[8];
    #pragma unroll
    for (int i = 0; i < 8; i++) {
        const int idx = tid + i * 128;
        xv[i] = *(const float4*)&X[(size_t)(m0 + (idx >> 4)) * H_IN + (idx & 15) * 4];
    }

    for (int kk = 0; kk < H_IN; kk += 64) {
        float4 wv[8];
        #pragma unroll
        for (int i = 0; i < 8; i++) {
            const int idx = tid + i * 128;
            wv[i] = *(const float4*)&W[(size_t)(kk + (idx >> 4)) * D + (idx & 15) * 4];
        }
        #pragma unroll
        for (int i = 0; i < 8; i++) {
            const int idx = tid + i * 128;
            const int row = idx >> 4, f4 = idx & 15;
            uint2 hi, lo; split4(xv[i], hi, lo);
            *(uint2*)&Ah[row * LDB + f4 * 4] = hi;
            *(uint2*)&Al[row * LDB + f4 * 4] = lo;
        }
        #pragma unroll
        for (int i = 0; i < 8; i++) {
            const int idx = tid + i * 128;
            const int row = idx >> 4, f4 = idx & 15;
            uint2 hi, lo; split4(wv[i], hi, lo);
            *(uint2*)&Bh[row * LDB + f4 * 4] = hi;
            *(uint2*)&Bl[row * LDB + f4 * 4] = lo;
        }
        __syncthreads();

        if (kk + 64 < H_IN) {
            #pragma unroll
            for (int i = 0; i < 8; i++) {
                const int idx = tid + i * 128;
                xv[i] = *(const float4*)&X[(size_t)(m0 + (idx >> 4)) * H_IN + kk + 64 + (idx & 15) * 4];
            }
        }

        uint32_t ah[4], al[4], bb[4], bl[4];
        #pragma unroll
        for (int kt = 0; kt < 4; kt++) {
            const int aoff = (w * 16 + (lane & 15)) * LDB + kt * 16 + (lane >> 4) * 8;
            ldsm_x4(ah, s2u(&Ah[aoff]));
            ldsm_x4(al, s2u(&Al[aoff]));
            #pragma unroll
            for (int p = 0; p < 4; p++) {
                const int row = kt * 16 + (g & 1) * 8 + l8;
                const int col = (2 * p + (g >> 1)) * 8;
                ldsm_x4_t(bb, s2u(&Bh[row * LDB + col]));
                ldsm_x4_t(bl, s2u(&Bl[row * LDB + col]));
                mma16816(acc[2*p],   ah, bb);     mma16816(acc[2*p],   ah, bl);
                mma16816(acc[2*p],   al, bb);
                mma16816(acc[2*p+1], ah, bb + 2); mma16816(acc[2*p+1], ah, bl + 2);
                mma16816(acc[2*p+1], al, bb + 2);
            }
        }
        __syncthreads();
    }

    const int r0 = m0 + w * 16 + (lane >> 2);
    #pragma unroll
    for (int nt = 0; nt < 8; nt++) {
        const int c = nt * 8 + (lane & 3) * 2;
        const float2 b2 = *(const float2*)&Bias[c];
        const float y0 = (acc[nt][0] + b2.x) * scale;
        const float y1 = (acc[nt][1] + b2.y) * scale;
        const float y2 = (acc[nt][2] + b2.x) * scale;
        const float y3 = (acc[nt][3] + b2.y) * scale;
        *(uint32_t*)&outH[(size_t)r0 * D + c]       = pack_hi(y0, y1);
        *(uint32_t*)&outL[(size_t)r0 * D + c]       = pack_lo(y0, y1);
        *(uint32_t*)&outH[(size_t)(r0 + 8) * D + c] = pack_hi(y2, y3);
        *(uint32_t*)&outL[(size_t)(r0 + 8) * D + c] = pack_lo(y2, y3);
    }
}

// ---------------------------------------------------------------------------
// Kernel 2: flash attention. 128 threads (4 warps), 32-row Q tile -> grid 256,
// 2 CTAs/SM so independent CTAs overlap MMA with softmax phases.
// Warp = (row-group rg = w&1: 16 rows) x (KV half kh = w>>1: 32 cols).
// 2-stage cp.async pipeline; single softmax barrier; PV uses FULL split P.
// ---------------------------------------------------------------------------
__device__ __forceinline__ void issue_kv(uint16_t* ST, int st, int n, int t, int tid)
{
    const int tile = tid >> 5;          // 0:Kh 1:Kl 2:Vh 3:Vl
    const int cc0  = tid & 31;
    const uint16_t* gp = (tile == 0) ? g_kh : (tile == 1) ? g_kl
                        : (tile == 2) ? g_vh : g_vl;
    uint16_t* sp = ST + (size_t)(st * 4 + tile) * 64 * LDB;
    const size_t gbase = ((size_t)n * LSEQ + (size_t)t * 64) * D;
    #pragma unroll
    for (int j = 0; j < 16; j++) {
        const int cc  = cc0 + j * 32;
        const int row = cc >> 3, col = (cc & 7) * 8;
        cp16(s2u(&sp[row * LDB + col]), &gp[gbase + (size_t)row * D + col]);
    }
    cp_commit();
}

__global__ __launch_bounds__(128) void attn_mma(float* __restrict__ out)
{
    extern __shared__ uint16_t sa[];
    uint16_t* Qh = sa;                            // [32][LDB]
    uint16_t* Ql = Qh + 32 * LDB;
    uint16_t* ST = Ql + 32 * LDB;                 // 8 KV tiles (2 stages x {Kh,Kl,Vh,Vl})
    float2* red = (float2*)(ST + 8 * 64 * LDB);   // [2][32] of (max, sum)

    const int tid  = threadIdx.x;
    const int lane = tid & 31;
    const int w    = tid >> 5;
    const int rg   = w & 1;        // 16-row group
    const int kh   = w >> 1;       // KV half
    const int g    = lane >> 3, l8 = lane & 7;
    const int n    = blockIdx.y;
    const int q0   = blockIdx.x * 32;

    issue_kv(ST, 0, n, 0, tid);

    // load Q hi/lo (pre-scaled). 32x64 elems = 256 8-elem units; 128 threads x 2.
    #pragma unroll
    for (int j = 0; j < 2; j++) {
        const uint16_t* gp = j ? g_ql : g_qh;
        uint16_t* spq = j ? Ql : Qh;
        #pragma unroll
        for (int i = 0; i < 2; i++) {
            const int cc = tid + i * 128;
            const int row = cc >> 3, col = (cc & 7) * 8;
            *(uint4*)&spq[row * LDB + col] =
                *(const uint4*)&gp[((size_t)(n * LSEQ + q0 + row)) * D + col];
        }
    }
    __syncthreads();

    uint32_t qh[4][4], ql[4][4];
    #pragma unroll
    for (int kt = 0; kt < 4; kt++) {
        const int aoff = (rg * 16 + (lane & 15)) * LDB + kt * 16 + (lane >> 4) * 8;
        ldsm_x4(qh[kt], s2u(&Qh[aoff]));
        ldsm_x4(ql[kt], s2u(&Ql[aoff]));
    }

    float o[8][4];
    #pragma unroll
    for (int nt = 0; nt < 8; nt++)
        #pragma unroll
        for (int j = 0; j < 4; j++) o[nt][j] = 0.f;
    float m0v = -1e30f, m1v = -1e30f, l0 = 0.f, l1 = 0.f;

    const int rrow = rg * 16 + (lane >> 2);   // row in [0,32) this lane owns (and +8)

    for (int t = 0; t < NTILES; t++) {
        const int st = t & 1;
        if (t + 1 < NTILES) { issue_kv(ST, (t + 1) & 1, n, t + 1, tid); cp_wait<1>(); }
        else                { cp_wait<0>(); }
        __syncthreads();   // B1: stage st ready

        uint16_t* sKh = ST + (size_t)(st * 4 + 0) * 64 * LDB;
        uint16_t* sKl = ST + (size_t)(st * 4 + 1) * 64 * LDB;
        uint16_t* sVh = ST + (size_t)(st * 4 + 2) * 64 * LDB;
        uint16_t* sVl = ST + (size_t)(st * 4 + 3) * 64 * LDB;

        // ---- S = Q @ K^T  (warp: 16 rows x 32 cols) ----
        float s[4][4];
        #pragma unroll
        for (int nt = 0; nt < 4; nt++)
            #pragma unroll
            for (int j = 0; j < 4; j++) s[nt][j] = 0.f;

        #pragma unroll
        for (int kt = 0; kt < 4; kt++) {
            uint32_t kb[4], kl_[4];
            #pragma unroll
            for (int p = 0; p < 2; p++) {
                const int row  = kh * 32 + p * 16 + (g >> 1) * 8 + l8;
                const int koff = kt * 16 + (g & 1) * 8;
                ldsm_x4(kb,  s2u(&sKh[row * LDB + koff]));
                ldsm_x4(kl_, s2u(&sKl[row * LDB + koff]));
                mma16816(s[2*p],   qh[kt], kb);     mma16816(s[2*p],   qh[kt], kl_);
                mma16816(s[2*p],   ql[kt], kb);
                mma16816(s[2*p+1], qh[kt], kb + 2); mma16816(s[2*p+1], qh[kt], kl_ + 2);
                mma16816(s[2*p+1], ql[kt], kb + 2);
            }
        }

        // ---- softmax: local max+exp+sum, ONE barrier to merge across kh pair ----
        float mx0 = -1e30f, mx1 = -1e30f;
        #pragma unroll
        for (int nt = 0; nt < 4; nt++) {
            mx0 = fmaxf(mx0, fmaxf(s[nt][0], s[nt][1]));
            mx1 = fmaxf(mx1, fmaxf(s[nt][2], s[nt][3]));
        }
        mx0 = fmaxf(mx0, __shfl_xor_sync(0xffffffffu, mx0, 1));
        mx0 = fmaxf(mx0, __shfl_xor_sync(0xffffffffu, mx0, 2));
        mx1 = fmaxf(mx1, __shfl_xor_sync(0xffffffffu, mx1, 1));
        mx1 = fmaxf(mx1, __shfl_xor_sync(0xffffffffu, mx1, 2));

        float rs0 = 0.f, rs1 = 0.f;
        #pragma unroll
        for (int nt = 0; nt < 4; nt++) {
            s[nt][0] = __expf(s[nt][0] - mx0); rs0 += s[nt][0];
            s[nt][1] = __expf(s[nt][1] - mx0); rs0 += s[nt][1];
            s[nt][2] = __expf(s[nt][2] - mx1); rs1 += s[nt][2];
            s[nt][3] = __expf(s[nt][3] - mx1); rs1 += s[nt][3];
        }
        rs0 += __shfl_xor_sync(0xffffffffu, rs0, 1);
        rs0 += __shfl_xor_sync(0xffffffffu, rs0, 2);
        rs1 += __shfl_xor_sync(0xffffffffu, rs1, 1);
        rs1 += __shfl_xor_sync(0xffffffffu, rs1, 2);

        if ((lane & 3) == 0) {
            red[kh * 32 + rrow]     = make_float2(mx0, rs0);
            red[kh * 32 + rrow + 8] = make_float2(mx1, rs1);
        }
        __syncthreads();   // B2 (single softmax barrier)
        const float2 p0 = red[(kh ^ 1) * 32 + rrow];
        const float2 p1 = red[(kh ^ 1) * 32 + rrow + 8];

        const float mn0 = fmaxf(m0v, fmaxf(mx0, p0.x));
        const float mn1 = fmaxf(m1v, fmaxf(mx1, p1.x));
        const float corr0 = __expf(m0v - mn0), corr1 = __expf(m1v - mn1);
        const float sc0 = __expf(mx0 - mn0),  sc1 = __expf(mx1 - mn1);
        l0 = l0 * corr0 + rs0 * sc0 + p0.y * __expf(p0.x - mn0);
        l1 = l1 * corr1 + rs1 * sc1 + p1.y * __expf(p1.x - mn1);
        m0v = mn0; m1v = mn1;
        #pragma unroll
        for (int nt = 0; nt < 4; nt++) {
            s[nt][0] *= sc0; s[nt][1] *= sc0;
            s[nt][2] *= sc1; s[nt][3] *= sc1;
        }
        #pragma unroll
        for (int nt = 0; nt < 8; nt++) {
            o[nt][0] *= corr0; o[nt][1] *= corr0;
            o[nt][2] *= corr1; o[nt][3] *= corr1;
        }

        // ---- O += P @ V  (FULL split P: ph*vh + ph*vl + pl*vh) ----
        #pragma unroll
        for (int kt = 0; kt < 2; kt++) {
            uint32_t ph[4], pl[4];
            ph[0] = pack_hi(s[2*kt][0],   s[2*kt][1]);
            ph[1] = pack_hi(s[2*kt][2],   s[2*kt][3]);
            ph[2] = pack_hi(s[2*kt+1][0], s[2*kt+1][1]);
            ph[3] = pack_hi(s[2*kt+1][2], s[2*kt+1][3]);
            pl[0] = pack_lo(s[2*kt][0],   s[2*kt][1]);
            pl[1] = pack_lo(s[2*kt][2],   s[2*kt][3]);
            pl[2] = pack_lo(s[2*kt+1][0], s[2*kt+1][1]);
            pl[3] = pack_lo(s[2*kt+1][2], s[2*kt+1][3]);
            #pragma unroll
            for (int p = 0; p < 4; p++) {
                const int row = kh * 32 + kt * 16 + (g & 1) * 8 + l8;
                const int col = (2 * p + (g >> 1)) * 8;
                uint32_t vb[4], vl_[4];
                ldsm_x4_t(vb,  s2u(&sVh[row * LDB + col]));
                ldsm_x4_t(vl_, s2u(&sVl[row * LDB + col]));
                mma16816(o[2*p],   ph, vb);     mma16816(o[2*p],   ph, vl_);
                mma16816(o[2*p],   pl, vb);
                mma16816(o[2*p+1], ph, vb + 2); mma16816(o[2*p+1], ph, vl_ + 2);
                mma16816(o[2*p+1], pl, vb + 2);
            }
        }
        __syncthreads();   // B3: reads of stage st done before t+1 overwrites it
    }

    // ---- combine the two KV-half partial O's, normalize, write ----
    float* Osm = (float*)ST;    // pipeline drained; reuse (32 x 66 floats)
    if (kh == 1) {
        #pragma unroll
        for (int nt = 0; nt < 8; nt++) {
            const int c = nt * 8 + (lane & 3) * 2;
            *(float2*)&Osm[rrow * 66 + c]       = make_float2(o[nt][0], o[nt][1]);
            *(float2*)&Osm[(rrow + 8) * 66 + c] = make_float2(o[nt][2], o[nt][3]);
        }
    }
    __syncthreads();
    if (kh == 0) {
        const float inv0 = 1.f / l0, inv1 = 1.f / l1;
        #pragma unroll
        for (int nt = 0; nt < 8; nt++) {
            const int c = nt * 8 + (lane & 3) * 2;
            const float2 a0 = *(float2*)&Osm[rrow * 66 + c];
            const float2 a1 = *(float2*)&Osm[(rrow + 8) * 66 + c];
            float2 o0 = make_float2((o[nt][0] + a0.x) * inv0, (o[nt][1] + a0.y) * inv0);
            float2 o1 = make_float2((o[nt][2] + a1.x) * inv1, (o[nt][3] + a1.y) * inv1);
            *(float2*)&out[((size_t)(n * LSEQ + q0 + rrow)) * D + c]     = o0;
            *(float2*)&out[((size_t)(n * LSEQ + q0 + rrow + 8)) * D + c] = o1;
        }
    }
}

// ---------------------------------------------------------------------------
// Launch
// ---------------------------------------------------------------------------
extern "C" void kernel_launch(void* const* d_in, const int* in_sizes, int n_in,
                              void* d_out, int out_size)
{
    const float* q  = (const float*)d_in[0];
    const float* k  = (const float*)d_in[1];
    const float* v  = (const float*)d_in[2];
    const float* Wq = (const float*)d_in[3];
    const float* bq = (const float*)d_in[4];
    const float* Wk = (const float*)d_in[5];
    const float* bk = (const float*)d_in[6];
    const float* Wv = (const float*)d_in[7];
    const float* bv = (const float*)d_in[8];
    float* out = (float*)d_out;

    const int smem_proj = 4 * 64 * LDB * 2;                            // 36864 B
    const int smem_attn = (2 * 32 + 8 * 64) * LDB * 2 + 64 * 8;       // 83456 B
    cudaFuncSetAttribute(proj_mma, cudaFuncAttributeMaxDynamicSharedMemorySize, smem_proj);
    cudaFuncSetAttribute(attn_mma, cudaFuncAttributeMaxDynamicSharedMemorySize, smem_attn);

    proj_mma<<<dim3(MROWS / 64, 3), 128, smem_proj>>>(q, k, v, Wq, Wk, Wv, bq, bk, bv);
    attn_mma<<<dim3(LSEQ / 32, NB), 128, smem_attn>>>(out);
}

// round 8
// speedup vs baseline: 1.2700x; 1.2700x over previous
#include <cuda_runtime.h>
#include <cstdint>

#define H_IN  1024
#define D     64
#define NB    4
#define LSEQ  2048
#define MROWS (NB*LSEQ)     // 8192
#define LDB   72            // smem row stride (bf16 elems): 144B
#define NTL   16            // KV tiles per CTA (half of 32)

// Pre-split projected tensors (hi/lo bf16). Q pre-scaled by 1/(8*ln2).
__device__ uint16_t g_qh[MROWS * D];
__device__ uint16_t g_ql[MROWS * D];
__device__ uint16_t g_kh[MROWS * D];
__device__ uint16_t g_kl[MROWS * D];
__device__ uint16_t g_vh[MROWS * D];
__device__ uint16_t g_vl[MROWS * D];
// Split-KV partials (unnormalized O and denominator l)
__device__ float g_p0[MROWS * D];
__device__ float g_p1[MROWS * D];
__device__ float g_l0[MROWS];
__device__ float g_l1[MROWS];

// ---------------------------------------------------------------------------
// helpers
// ---------------------------------------------------------------------------
__device__ __forceinline__ uint32_t s2u(const void* p) {
    uint32_t a;
    asm("{.reg .u64 t; cvta.to.shared.u64 t, %1; cvt.u32.u64 %0, t;}" : "=r"(a) : "l"(p));
    return a;
}
__device__ __forceinline__ void ldsm_x4(uint32_t* r, uint32_t addr) {
    asm volatile("ldmatrix.sync.aligned.m8n8.x4.shared.b16 {%0,%1,%2,%3}, [%4];"
                 : "=r"(r[0]), "=r"(r[1]), "=r"(r[2]), "=r"(r[3]) : "r"(addr));
}
__device__ __forceinline__ void ldsm_x4_t(uint32_t* r, uint32_t addr) {
    asm volatile("ldmatrix.sync.aligned.m8n8.x4.trans.shared.b16 {%0,%1,%2,%3}, [%4];"
                 : "=r"(r[0]), "=r"(r[1]), "=r"(r[2]), "=r"(r[3]) : "r"(addr));
}
__device__ __forceinline__ void mma16816(float* c, const uint32_t* a, const uint32_t* b) {
    asm volatile("mma.sync.aligned.m16n8k16.row.col.f32.bf16.bf16.f32 "
                 "{%0,%1,%2,%3}, {%4,%5,%6,%7}, {%8,%9}, {%0,%1,%2,%3};"
                 : "+f"(c[0]), "+f"(c[1]), "+f"(c[2]), "+f"(c[3])
                 : "r"(a[0]), "r"(a[1]), "r"(a[2]), "r"(a[3]), "r"(b[0]), "r"(b[1]));
}
__device__ __forceinline__ void split4(float4 v, uint2& hi, uint2& lo) {
    uint32_t ux = __float_as_uint(v.x), uy = __float_as_uint(v.y);
    uint32_t uz = __float_as_uint(v.z), uw = __float_as_uint(v.w);
    asm("prmt.b32 %0, %1, %2, 0x7632;" : "=r"(hi.x) : "r"(ux), "r"(uy));
    asm("prmt.b32 %0, %1, %2, 0x7632;" : "=r"(hi.y) : "r"(uz), "r"(uw));
    float rx = v.x - __uint_as_float(ux & 0xFFFF0000u);
    float ry = v.y - __uint_as_float(uy & 0xFFFF0000u);
    float rz = v.z - __uint_as_float(uz & 0xFFFF0000u);
    float rw = v.w - __uint_as_float(uw & 0xFFFF0000u);
    asm("cvt.rn.bf16x2.f32 %0, %1, %2;" : "=r"(lo.x) : "f"(ry), "f"(rx));
    asm("cvt.rn.bf16x2.f32 %0, %1, %2;" : "=r"(lo.y) : "f"(rw), "f"(rz));
}
__device__ __forceinline__ uint32_t pack_hi(float a, float b) {
    uint32_t r;
    asm("prmt.b32 %0, %1, %2, 0x7632;" : "=r"(r)
        : "r"(__float_as_uint(a)), "r"(__float_as_uint(b)));
    return r;
}
__device__ __forceinline__ uint32_t pack_lo(float a, float b) {
    float ra = a - __uint_as_float(__float_as_uint(a) & 0xFFFF0000u);
    float rb = b - __uint_as_float(__float_as_uint(b) & 0xFFFF0000u);
    uint32_t r;
    asm("cvt.rn.bf16x2.f32 %0, %1, %2;" : "=r"(r) : "f"(rb), "f"(ra));
    return r;
}
__device__ __forceinline__ float ex2(float x) {
    float y;
    asm("ex2.approx.f32 %0, %1;" : "=f"(y) : "f"(x));
    return y;
}
template <int N> __device__ __forceinline__ void cp_wait() {
    asm volatile("cp.async.wait_group %0;" :: "n"(N) : "memory");
}
__device__ __forceinline__ void cp_commit() {
    asm volatile("cp.async.commit_group;" ::: "memory");
}
__device__ __forceinline__ void cp16(uint32_t saddr, const void* gaddr) {
    asm volatile("cp.async.cg.shared.global [%0], [%1], 16;"
                 :: "r"(saddr), "l"(gaddr) : "memory");
}

// ---------------------------------------------------------------------------
// Kernel 1: QKV projection (unchanged structure; Q scale folds 1/ln2).
// ---------------------------------------------------------------------------
__global__ __launch_bounds__(128) void proj_mma(
    const float* __restrict__ Xq, const float* __restrict__ Xk, const float* __restrict__ Xv,
    const float* __restrict__ Wq, const float* __restrict__ Wk, const float* __restrict__ Wv,
    const float* __restrict__ Bq, const float* __restrict__ Bk, const float* __restrict__ Bv)
{
    const float* X; const float* W; const float* Bias;
    uint16_t* outH; uint16_t* outL; float scale;
    switch (blockIdx.y) {
        case 0:  X = Xq; W = Wq; Bias = Bq; outH = g_qh; outL = g_ql;
                 scale = 0.18033688f; break;             // 1/(8*ln2)
        case 1:  X = Xk; W = Wk; Bias = Bk; outH = g_kh; outL = g_kl; scale = 1.0f; break;
        default: X = Xv; W = Wv; Bias = Bv; outH = g_vh; outL = g_vl; scale = 1.0f; break;
    }

    extern __shared__ uint16_t sp[];
    uint16_t* Ah = sp;
    uint16_t* Al = Ah + 64 * LDB;
    uint16_t* Bh = Al + 64 * LDB;
    uint16_t* Bl = Bh + 64 * LDB;

    const int tid  = threadIdx.x;
    const int lane = tid & 31;
    const int w    = tid >> 5;
    const int m0   = blockIdx.x * 64;
    const int g    = lane >> 3, l8 = lane & 7;

    float acc[8][4];
    #pragma unroll
    for (int nt = 0; nt < 8; nt++)
        #pragma unroll
        for (int j = 0; j < 4; j++) acc[nt][j] = 0.f;

    float4 xv[8];
    #pragma unroll
    for (int i = 0; i < 8; i++) {
        const int idx = tid + i * 128;
        xv[i] = *(const float4*)&X[(size_t)(m0 + (idx >> 4)) * H_IN + (idx & 15) * 4];
    }

    for (int kk = 0; kk < H_IN; kk += 64) {
        float4 wv[8];
        #pragma unroll
        for (int i = 0; i < 8; i++) {
            const int idx = tid + i * 128;
            wv[i] = *(const float4*)&W[(size_t)(kk + (idx >> 4)) * D + (idx & 15) * 4];
        }
        #pragma unroll
        for (int i = 0; i < 8; i++) {
            const int idx = tid + i * 128;
            const int row = idx >> 4, f4 = idx & 15;
            uint2 hi, lo; split4(xv[i], hi, lo);
            *(uint2*)&Ah[row * LDB + f4 * 4] = hi;
            *(uint2*)&Al[row * LDB + f4 * 4] = lo;
        }
        #pragma unroll
        for (int i = 0; i < 8; i++) {
            const int idx = tid + i * 128;
            const int row = idx >> 4, f4 = idx & 15;
            uint2 hi, lo; split4(wv[i], hi, lo);
            *(uint2*)&Bh[row * LDB + f4 * 4] = hi;
            *(uint2*)&Bl[row * LDB + f4 * 4] = lo;
        }
        __syncthreads();

        if (kk + 64 < H_IN) {
            #pragma unroll
            for (int i = 0; i < 8; i++) {
                const int idx = tid + i * 128;
                xv[i] = *(const float4*)&X[(size_t)(m0 + (idx >> 4)) * H_IN + kk + 64 + (idx & 15) * 4];
            }
        }

        uint32_t ah[4], al[4], bb[4], bl[4];
        #pragma unroll
        for (int kt = 0; kt < 4; kt++) {
            const int aoff = (w * 16 + (lane & 15)) * LDB + kt * 16 + (lane >> 4) * 8;
            ldsm_x4(ah, s2u(&Ah[aoff]));
            ldsm_x4(al, s2u(&Al[aoff]));
            #pragma unroll
            for (int p = 0; p < 4; p++) {
                const int row = kt * 16 + (g & 1) * 8 + l8;
                const int col = (2 * p + (g >> 1)) * 8;
                ldsm_x4_t(bb, s2u(&Bh[row * LDB + col]));
                ldsm_x4_t(bl, s2u(&Bl[row * LDB + col]));
                mma16816(acc[2*p],   ah, bb);     mma16816(acc[2*p],   ah, bl);
                mma16816(acc[2*p],   al, bb);
                mma16816(acc[2*p+1], ah, bb + 2); mma16816(acc[2*p+1], ah, bl + 2);
                mma16816(acc[2*p+1], al, bb + 2);
            }
        }
        __syncthreads();
    }

    const int r0 = m0 + w * 16 + (lane >> 2);
    #pragma unroll
    for (int nt = 0; nt < 8; nt++) {
        const int c = nt * 8 + (lane & 3) * 2;
        const float2 b2 = *(const float2*)&Bias[c];
        const float y0 = (acc[nt][0] + b2.x) * scale;
        const float y1 = (acc[nt][1] + b2.y) * scale;
        const float y2 = (acc[nt][2] + b2.x) * scale;
        const float y3 = (acc[nt][3] + b2.y) * scale;
        *(uint32_t*)&outH[(size_t)r0 * D + c]       = pack_hi(y0, y1);
        *(uint32_t*)&outL[(size_t)r0 * D + c]       = pack_lo(y0, y1);
        *(uint32_t*)&outH[(size_t)(r0 + 8) * D + c] = pack_hi(y2, y3);
        *(uint32_t*)&outL[(size_t)(r0 + 8) * D + c] = pack_lo(y2, y3);
    }
}

// ---------------------------------------------------------------------------
// Kernel 2: flash attention, split-KV(2), no-max softmax (base-2).
// CTA: 4 warps, 64 Q rows (warp = 16 rows x full 64-col KV tile).
// grid (32, 4, 2): z = KV half. 2 CTAs/SM. Writes unnormalized partials.
// ---------------------------------------------------------------------------
#define STG 36864           // one KV stage: 4 arrays x 64 x 144B
#define ARR 9216

__device__ __forceinline__ void issue_kv(uint32_t kvb, int n, int tile, int tid) {
    #pragma unroll
    for (int j = 0; j < 16; j++) {
        const int cc = tid + j * 128;
        const int arr = cc >> 9, rem = cc & 511, row = rem >> 3, col = rem & 7;
        const uint16_t* gp = (arr == 0) ? g_kh : (arr == 1) ? g_kl
                            : (arr == 2) ? g_vh : g_vl;
        cp16(kvb + arr * ARR + row * 144 + col * 16,
             gp + ((size_t)(n * LSEQ + tile * 64 + row)) * D + col * 8);
    }
    cp_commit();
}

__global__ __launch_bounds__(128) void attn_mma(void)
{
    extern __shared__ uint16_t sa[];
    uint16_t* Qh = sa;                      // [64][LDB]
    uint16_t* Ql = Qh + 64 * LDB;
    uint16_t* KV = Ql + 64 * LDB;           // 2 stages x {Kh,Kl,Vh,Vl}[64][LDB]
    const uint32_t kvb = s2u(KV);

    const int tid  = threadIdx.x;
    const int lane = tid & 31;
    const int w    = tid >> 5;
    const int g    = lane >> 3, l8 = lane & 7;
    const int n    = blockIdx.y;
    const int q0   = blockIdx.x * 64;
    const int z    = blockIdx.z;
    const int off  = (blockIdx.x * 7 + blockIdx.y * 5 + z * 3) & (NTL - 1);
    #define TL(t) (z * NTL + (((t) + off) & (NTL - 1)))

    float* gP = z ? g_p1 : g_p0;
    float* gL = z ? g_l1 : g_l0;

    // prologue: tile0 async; Q direct
    issue_kv(kvb + 0 * STG, n, TL(0), tid);
    #pragma unroll
    for (int j = 0; j < 8; j++) {
        const int cc = tid + j * 128;
        const int a = cc >> 9, rem = cc & 511, row = rem >> 3, col = rem & 7;
        uint16_t* spq = a ? Ql : Qh;
        *(uint4*)&spq[row * LDB + col * 8] =
            *(const uint4*)&(a ? g_ql : g_qh)[((size_t)(n * LSEQ + q0 + row)) * D + col * 8];
    }
    __syncthreads();

    uint32_t qh[4][4], ql[4][4];
    #pragma unroll
    for (int kt = 0; kt < 4; kt++) {
        const int aoff = (w * 16 + (lane & 15)) * LDB + kt * 16 + (lane >> 4) * 8;
        ldsm_x4(qh[kt], s2u(&Qh[aoff]));
        ldsm_x4(ql[kt], s2u(&Ql[aoff]));
    }

    float o[8][4];
    #pragma unroll
    for (int nt = 0; nt < 8; nt++)
        #pragma unroll
        for (int j = 0; j < 4; j++) o[nt][j] = 0.f;
    float l0 = 0.f, l1 = 0.f;

    for (int t = 0; t < NTL; t++) {
        const uint32_t st = kvb + (t & 1) * STG;
        if (t + 1 < NTL) { issue_kv(kvb + ((t + 1) & 1) * STG, n, TL(t + 1), tid); cp_wait<1>(); }
        else             { cp_wait<0>(); }
        __syncthreads();                       // stage (t&1) ready

        // ---- S = Q @ K^T (16 x 64), 3-term split ----
        float s[8][4];
        #pragma unroll
        for (int nt = 0; nt < 8; nt++)
            #pragma unroll
            for (int j = 0; j < 4; j++) s[nt][j] = 0.f;

        #pragma unroll
        for (int kt = 0; kt < 4; kt++) {
            #pragma unroll
            for (int p = 0; p < 4; p++) {
                const int row  = p * 16 + (g >> 1) * 8 + l8;
                const int koff = kt * 16 + (g & 1) * 8;
                uint32_t kb[4], kl_[4];
                ldsm_x4(kb,  st + 0 * ARR + (row * LDB + koff) * 2);
                ldsm_x4(kl_, st + 1 * ARR + (row * LDB + koff) * 2);
                mma16816(s[2*p],   qh[kt], kb);     mma16816(s[2*p],   qh[kt], kl_);
                mma16816(s[2*p],   ql[kt], kb);
                mma16816(s[2*p+1], qh[kt], kb + 2); mma16816(s[2*p+1], qh[kt], kl_ + 2);
                mma16816(s[2*p+1], ql[kt], kb + 2);
            }
        }

        // ---- softmax, no max: p = 2^s (Q pre-scaled by 1/(8 ln2)) ----
        float rs0 = 0.f, rs1 = 0.f;
        #pragma unroll
        for (int nt = 0; nt < 8; nt++) {
            s[nt][0] = ex2(s[nt][0]); rs0 += s[nt][0];
            s[nt][1] = ex2(s[nt][1]); rs0 += s[nt][1];
            s[nt][2] = ex2(s[nt][2]); rs1 += s[nt][2];
            s[nt][3] = ex2(s[nt][3]); rs1 += s[nt][3];
        }
        rs0 += __shfl_xor_sync(0xffffffffu, rs0, 1);
        rs0 += __shfl_xor_sync(0xffffffffu, rs0, 2);
        rs1 += __shfl_xor_sync(0xffffffffu, rs1, 1);
        rs1 += __shfl_xor_sync(0xffffffffu, rs1, 2);
        l0 += rs0;
        l1 += rs1;

        // ---- O += P @ V, 3-term split ----
        #pragma unroll
        for (int kt = 0; kt < 4; kt++) {
            uint32_t ph[4], pl[4];
            ph[0] = pack_hi(s[2*kt][0],   s[2*kt][1]);
            ph[1] = pack_hi(s[2*kt][2],   s[2*kt][3]);
            ph[2] = pack_hi(s[2*kt+1][0], s[2*kt+1][1]);
            ph[3] = pack_hi(s[2*kt+1][2], s[2*kt+1][3]);
            pl[0] = pack_lo(s[2*kt][0],   s[2*kt][1]);
            pl[1] = pack_lo(s[2*kt][2],   s[2*kt][3]);
            pl[2] = pack_lo(s[2*kt+1][0], s[2*kt+1][1]);
            pl[3] = pack_lo(s[2*kt+1][2], s[2*kt+1][3]);
            #pragma unroll
            for (int p = 0; p < 4; p++) {
                const int row = kt * 16 + (g & 1) * 8 + l8;
                const int col = (2 * p + (g >> 1)) * 8;
                uint32_t vb[4], vl_[4];
                ldsm_x4_t(vb,  st + 2 * ARR + (row * LDB + col) * 2);
                ldsm_x4_t(vl_, st + 3 * ARR + (row * LDB + col) * 2);
                mma16816(o[2*p],   ph, vb);     mma16816(o[2*p],   ph, vl_);
                mma16816(o[2*p],   pl, vb);
                mma16816(o[2*p+1], ph, vb + 2); mma16816(o[2*p+1], ph, vl_ + 2);
                mma16816(o[2*p+1], pl, vb + 2);
            }
        }
        __syncthreads();                       // stage reads done
    }

    // ---- write unnormalized partial O and l ----
    const int r = q0 + w * 16 + (lane >> 2);
    #pragma unroll
    for (int nt = 0; nt < 8; nt++) {
        const int c = nt * 8 + (lane & 3) * 2;
        *(float2*)&gP[((size_t)(n * LSEQ + r)) * D + c]     = make_float2(o[nt][0], o[nt][1]);
        *(float2*)&gP[((size_t)(n * LSEQ + r + 8)) * D + c] = make_float2(o[nt][2], o[nt][3]);
    }
    if ((lane & 3) == 0) {
        gL[n * LSEQ + r]     = l0;
        gL[n * LSEQ + r + 8] = l1;
    }
}

// ---------------------------------------------------------------------------
// Kernel 3: combine the two KV halves: out = (P0+P1)/(l0+l1)
// ---------------------------------------------------------------------------
__global__ __launch_bounds__(256) void combine_k(float* __restrict__ out)
{
    const int id = blockIdx.x * 256 + threadIdx.x;   // 512 blocks x 256 = 131072 float4s
    const int e0 = id * 4;
    const int row = e0 >> 6, c = e0 & 63;
    const float inv = 1.f / (g_l0[row] + g_l1[row]);
    const float4 a = *(const float4*)&g_p0[(size_t)row * D + c];
    const float4 b = *(const float4*)&g_p1[(size_t)row * D + c];
    float4 r;
    r.x = (a.x + b.x) * inv; r.y = (a.y + b.y) * inv;
    r.z = (a.z + b.z) * inv; r.w = (a.w + b.w) * inv;
    *(float4*)&out[(size_t)row * D + c] = r;
}

// ---------------------------------------------------------------------------
// Launch
// ---------------------------------------------------------------------------
extern "C" void kernel_launch(void* const* d_in, const int* in_sizes, int n_in,
                              void* d_out, int out_size)
{
    const float* q  = (const float*)d_in[0];
    const float* k  = (const float*)d_in[1];
    const float* v  = (const float*)d_in[2];
    const float* Wq = (const float*)d_in[3];
    const float* bq = (const float*)d_in[4];
    const float* Wk = (const float*)d_in[5];
    const float* bk = (const float*)d_in[6];
    const float* Wv = (const float*)d_in[7];
    const float* bv = (const float*)d_in[8];
    float* out = (float*)d_out;

    const int smem_proj = 4 * 64 * LDB * 2;                 // 36864 B
    const int smem_attn = 2 * 64 * LDB * 2 + 2 * STG;       // 92160 B
    cudaFuncSetAttribute(proj_mma, cudaFuncAttributeMaxDynamicSharedMemorySize, smem_proj);
    cudaFuncSetAttribute(attn_mma, cudaFuncAttributeMaxDynamicSharedMemorySize, smem_attn);

    proj_mma<<<dim3(MROWS / 64, 3), 128, smem_proj>>>(q, k, v, Wq, Wk, Wv, bq, bk, bv);
    attn_mma<<<dim3(LSEQ / 64, NB, 2), 128, smem_attn>>>();
    combine_k<<<512, 256>>>(out);
}